// round 2
// baseline (speedup 1.0000x reference)
#include <cuda_runtime.h>
#include <cuda_bf16.h>
#include <math.h>

// ---------------------------------------------------------------------------
// QuanvolutionClassifier: quanv (4-qubit circuit per 2x2 patch) -> MLP 784->128
// relu -> 128->10 -> log_softmax.   All fp32.
// ---------------------------------------------------------------------------

#define MAX_B 4096
__device__ float g_feats[MAX_B * 784];   // scratch: quanv features [B, 784]

// ============================ Kernel 1: quanv ==============================
// One thread per (batch, patch). 16-amplitude real statevector in registers.
__global__ __launch_bounds__(256) void quanv_kernel(
    const float* __restrict__ x,      // [B, 784] (28x28)
    const float* __restrict__ theta,  // [2, 4]
    float* __restrict__ feats,        // [B, 784] out, feature idx = p*4 + w
    int B)
{
    int idx = blockIdx.x * blockDim.x + threadIdx.x;
    int total = B * 196;
    if (idx >= total) return;
    int b = idx / 196;
    int p = idx - b * 196;
    int r14 = p / 14;
    int c14 = p - r14 * 14;

    const float* xb = x + (size_t)b * 784 + (r14 * 2) * 28 + c14 * 2;
    float px0 = xb[0], px1 = xb[1], px2 = xb[28], px3 = xb[29];

    float c[4], s[4];
    __sincosf(0.5f * px0, &s[0], &c[0]);
    __sincosf(0.5f * px1, &s[1], &c[1]);
    __sincosf(0.5f * px2, &s[2], &c[2]);
    __sincosf(0.5f * px3, &s[3], &c[3]);

    // product state; wire w bit mask = 8 >> w (wire0 = MSB)
    float st[16];
#pragma unroll
    for (int i = 0; i < 16; i++) {
        float v = (i & 8) ? s[0] : c[0];
        v *= (i & 4) ? s[1] : c[1];
        v *= (i & 2) ? s[2] : c[2];
        v *= (i & 1) ? s[3] : c[3];
        st[i] = v;
    }

    // theta rotations (uniform per launch; broadcast loads)
    float tc[8], ts[8];
#pragma unroll
    for (int t = 0; t < 8; t++) {
        float th = __ldg(&theta[t]);
        __sincosf(0.5f * th, &ts[t], &tc[t]);
    }

#pragma unroll
    for (int l = 0; l < 2; l++) {
        // RY(theta[l][w]) on each wire
#pragma unroll
        for (int w = 0; w < 4; w++) {
            float cc = tc[l * 4 + w], ss = ts[l * 4 + w];
            int mask = 8 >> w;
#pragma unroll
            for (int i = 0; i < 16; i++) {
                if (i & mask) continue;
                int j = i | mask;
                float a0 = st[i], a1 = st[j];
                st[i] = cc * a0 - ss * a1;
                st[j] = ss * a0 + cc * a1;
            }
        }
        // CNOT ring (0,1),(1,2),(2,3),(3,0)
#pragma unroll
        for (int w = 0; w < 4; w++) {
            int cm = 8 >> w;
            int tm = 8 >> ((w + 1) & 3);
#pragma unroll
            for (int i = 0; i < 16; i++) {
                if ((i & cm) && !(i & tm)) {
                    int j = i | tm;
                    float t0 = st[i]; st[i] = st[j]; st[j] = t0;
                }
            }
        }
    }

    // PauliZ expectations
    float pr[16];
#pragma unroll
    for (int i = 0; i < 16; i++) pr[i] = st[i] * st[i];
    float o[4];
#pragma unroll
    for (int w = 0; w < 4; w++) {
        int mask = 8 >> w;
        float z = 0.f;
#pragma unroll
        for (int i = 0; i < 16; i++) z += (i & mask) ? -pr[i] : pr[i];
        o[w] = z;
    }
    float4 ov = make_float4(o[0], o[1], o[2], o[3]);
    *reinterpret_cast<float4*>(feats + (size_t)b * 784 + p * 4) = ov;
}

// ====================== Kernel 2: fused MLP + log_softmax ==================
// Block tile: 32 rows x 128 cols of h; thread tile 2x8; K chunks of 56.
// Epilogue: bias+relu, 128->10 GEMM partials, shfl-reduce, log_softmax.
#define BR 32
#define KT 56
#define NC 128

__global__ __launch_bounds__(256) void mlp_kernel(
    const float* __restrict__ feats,  // [B, 784]
    const float* __restrict__ W1,     // [784, 128]
    const float* __restrict__ b1,     // [128]
    const float* __restrict__ W2,     // [128, 10]
    const float* __restrict__ b2,     // [10]
    float* __restrict__ out,          // [B, 10]
    int B)
{
    __shared__ float sA[BR][KT + 1];   // feats tile, padded
    __shared__ float sB[KT][NC];       // W1 tile
    __shared__ float sW2[NC * 10];
    __shared__ float sb1[NC];

    int tid = threadIdx.x;
    int tc = tid & 15;    // col group: cols tc*8 .. tc*8+7
    int tr = tid >> 4;    // row group: rows tr*2, tr*2+1
    int row0 = blockIdx.x * BR;

    for (int i = tid; i < NC * 10; i += 256) sW2[i] = W2[i];
    if (tid < NC) sb1[tid] = b1[tid];

    float acc[2][8];
#pragma unroll
    for (int a = 0; a < 2; a++)
#pragma unroll
        for (int j = 0; j < 8; j++) acc[a][j] = 0.f;

    for (int k0 = 0; k0 < 784; k0 += KT) {
        __syncthreads();
        // load feats tile [BR][KT]
        for (int i = tid; i < BR * KT; i += 256) {
            int r = i / KT, k = i - r * KT;
            int row = row0 + r;
            sA[r][k] = (row < B) ? feats[(size_t)row * 784 + k0 + k] : 0.f;
        }
        // load W1 tile [KT][NC] (contiguous)
        for (int i = tid; i < KT * NC; i += 256) {
            (&sB[0][0])[i] = W1[(size_t)k0 * NC + i];
        }
        __syncthreads();
#pragma unroll 8
        for (int k = 0; k < KT; k++) {
            float a0 = sA[tr * 2 + 0][k];
            float a1 = sA[tr * 2 + 1][k];
            float4 bv0 = *reinterpret_cast<const float4*>(&sB[k][tc * 8]);
            float4 bv1 = *reinterpret_cast<const float4*>(&sB[k][tc * 8 + 4]);
            float bb[8] = {bv0.x, bv0.y, bv0.z, bv0.w, bv1.x, bv1.y, bv1.z, bv1.w};
#pragma unroll
            for (int j = 0; j < 8; j++) {
                acc[0][j] = fmaf(a0, bb[j], acc[0][j]);
                acc[1][j] = fmaf(a1, bb[j], acc[1][j]);
            }
        }
    }

    // epilogue: bias + relu + second GEMM partials
    float lg[2][10];
#pragma unroll
    for (int a = 0; a < 2; a++)
#pragma unroll
        for (int q = 0; q < 10; q++) lg[a][q] = 0.f;

#pragma unroll
    for (int j = 0; j < 8; j++) {
        int col = tc * 8 + j;
        float bias = sb1[col];
#pragma unroll
        for (int a = 0; a < 2; a++) {
            float h = acc[a][j] + bias;
            h = h > 0.f ? h : 0.f;
#pragma unroll
            for (int q = 0; q < 10; q++)
                lg[a][q] = fmaf(h, sW2[col * 10 + q], lg[a][q]);
        }
    }

    // reduce partial logits across the 16 col-group lanes (same half-warp)
#pragma unroll
    for (int off = 8; off; off >>= 1) {
#pragma unroll
        for (int a = 0; a < 2; a++)
#pragma unroll
            for (int q = 0; q < 10; q++)
                lg[a][q] += __shfl_xor_sync(0xffffffffu, lg[a][q], off);
    }

    if (tc == 0) {
#pragma unroll
        for (int a = 0; a < 2; a++) {
            int row = row0 + tr * 2 + a;
            if (row < B) {
                float l[10];
                float m = -1e30f;
#pragma unroll
                for (int q = 0; q < 10; q++) {
                    l[q] = lg[a][q] + __ldg(&b2[q]);
                    m = fmaxf(m, l[q]);
                }
                float se = 0.f;
#pragma unroll
                for (int q = 0; q < 10; q++) se += expf(l[q] - m);
                float lse = m + logf(se);
#pragma unroll
                for (int q = 0; q < 10; q++)
                    out[(size_t)row * 10 + q] = l[q] - lse;
            }
        }
    }
}

// ================================ launch ===================================
extern "C" void kernel_launch(void* const* d_in, const int* in_sizes, int n_in,
                              void* d_out, int out_size) {
    const float* x     = (const float*)d_in[0];   // [B, 784]
    const float* theta = (const float*)d_in[1];   // [2, 4]
    const float* W1    = (const float*)d_in[2];   // [784, 128]
    const float* b1    = (const float*)d_in[3];   // [128]
    const float* W2    = (const float*)d_in[4];   // [128, 10]
    const float* b2    = (const float*)d_in[5];   // [10]
    float* out = (float*)d_out;

    int B = in_sizes[0] / 784;
    if (B > MAX_B) B = MAX_B;

    float* feats;
    cudaGetSymbolAddress((void**)&feats, g_feats);

    int total = B * 196;
    int blocks1 = (total + 255) / 256;
    quanv_kernel<<<blocks1, 256>>>(x, theta, feats, B);

    int blocks2 = (B + BR - 1) / BR;
    mlp_kernel<<<blocks2, 256>>>(feats, W1, b1, W2, b2, out, B);
}

// round 5
// speedup vs baseline: 2.5303x; 2.5303x over previous
#include <cuda_runtime.h>
#include <cuda_bf16.h>
#include <math.h>

// ---------------------------------------------------------------------------
// QuanvolutionClassifier: quanv (4-qubit circuit per 2x2 patch) -> MLP 784->128
// relu -> 128->10 -> log_softmax.   All fp32.
// ---------------------------------------------------------------------------

#define MAX_B 4096
__device__ float g_feats[MAX_B * 784];   // scratch: quanv features [B, 784]

// ============================ Kernel 1: quanv ==============================
__global__ __launch_bounds__(256) void quanv_kernel(
    const float* __restrict__ x,      // [B, 784] (28x28)
    const float* __restrict__ theta,  // [2, 4]
    float* __restrict__ feats,        // [B, 784]
    int B)
{
    int idx = blockIdx.x * blockDim.x + threadIdx.x;
    int total = B * 196;
    if (idx >= total) return;
    int b = idx / 196;
    int p = idx - b * 196;
    int r14 = p / 14;
    int c14 = p - r14 * 14;

    const float* xb = x + (size_t)b * 784 + (r14 * 2) * 28 + c14 * 2;
    float2 t0 = *reinterpret_cast<const float2*>(xb);
    float2 t1 = *reinterpret_cast<const float2*>(xb + 28);
    float px0 = t0.x, px1 = t0.y, px2 = t1.x, px3 = t1.y;

    float c[4], s[4];
    __sincosf(0.5f * px0, &s[0], &c[0]);
    __sincosf(0.5f * px1, &s[1], &c[1]);
    __sincosf(0.5f * px2, &s[2], &c[2]);
    __sincosf(0.5f * px3, &s[3], &c[3]);

    float st[16];
#pragma unroll
    for (int i = 0; i < 16; i++) {
        float v = (i & 8) ? s[0] : c[0];
        v *= (i & 4) ? s[1] : c[1];
        v *= (i & 2) ? s[2] : c[2];
        v *= (i & 1) ? s[3] : c[3];
        st[i] = v;
    }

    float tc[8], ts[8];
#pragma unroll
    for (int t = 0; t < 8; t++) {
        float th = __ldg(&theta[t]);
        __sincosf(0.5f * th, &ts[t], &tc[t]);
    }

#pragma unroll
    for (int l = 0; l < 2; l++) {
#pragma unroll
        for (int w = 0; w < 4; w++) {
            float cc = tc[l * 4 + w], ss = ts[l * 4 + w];
            int mask = 8 >> w;
#pragma unroll
            for (int i = 0; i < 16; i++) {
                if (i & mask) continue;
                int j = i | mask;
                float a0 = st[i], a1 = st[j];
                st[i] = cc * a0 - ss * a1;
                st[j] = ss * a0 + cc * a1;
            }
        }
#pragma unroll
        for (int w = 0; w < 4; w++) {
            int cm = 8 >> w;
            int tm = 8 >> ((w + 1) & 3);
#pragma unroll
            for (int i = 0; i < 16; i++) {
                if ((i & cm) && !(i & tm)) {
                    int j = i | tm;
                    float t0s = st[i]; st[i] = st[j]; st[j] = t0s;
                }
            }
        }
    }

    float pr[16];
#pragma unroll
    for (int i = 0; i < 16; i++) pr[i] = st[i] * st[i];
    float o[4];
#pragma unroll
    for (int w = 0; w < 4; w++) {
        int mask = 8 >> w;
        float z = 0.f;
#pragma unroll
        for (int i = 0; i < 16; i++) z += (i & mask) ? -pr[i] : pr[i];
        o[w] = z;
    }
    *reinterpret_cast<float4*>(feats + (size_t)b * 784 + p * 4) =
        make_float4(o[0], o[1], o[2], o[3]);
}

// ====================== Kernel 2: fused MLP + log_softmax ==================
// 256 threads. Block = 32 rows x 128 cols of h. Thread tile 2x8.
// tc = tid>>4 (col group, 8 cols), tr = tid&15 (rows 2tr, 2tr+1).
// Register-prefetch pipelining over 14 K-chunks of 56.
#define BR 32
#define KT 56
#define NCHUNK 14
#define SA_STRIDE 57   // odd pad -> conflict-free A reads (18*tr mod 32 perm)
#define SH_STRIDE 132  // h staging stride (float4-aligned)

__global__ __launch_bounds__(256, 1) void mlp_kernel(
    const float* __restrict__ feats,  // [B, 784]
    const float* __restrict__ W1,     // [784, 128]
    const float* __restrict__ b1,     // [128]
    const float* __restrict__ W2,     // [128, 10]
    const float* __restrict__ b2,     // [10]
    float* __restrict__ out,          // [B, 10]
    int B)
{
    __shared__ float sA[BR * SA_STRIDE];        // 1824 floats
    __shared__ float sB[KT * 128];              // 7168 floats (reused as sH)
    __shared__ float sW2t[10 * 128];            // W2 transposed [q][col]
    __shared__ float sb1v[128];

    int tid = threadIdx.x;
    int tr = tid & 15;
    int tc = tid >> 4;
    int row0 = blockIdx.x * BR;

    for (int i = tid; i < 1280; i += 256) {
        int q = i >> 7, c = i & 127;
        sW2t[i] = W2[c * 10 + q];
    }
    if (tid < 128) sb1v[tid] = b1[tid];

    const float4* W1v4 = reinterpret_cast<const float4*>(W1);

    float acc[2][8];
#pragma unroll
    for (int a = 0; a < 2; a++)
#pragma unroll
        for (int j = 0; j < 8; j++) acc[a][j] = 0.f;

    float ra[7];
    float4 rb[7];

    // ---- prefetch chunk 0 ----
#pragma unroll
    for (int j = 0; j < 7; j++) {
        int i = tid + j * 256;
        int r = i / KT, k = i - r * KT;
        int row = row0 + r;
        ra[j] = (row < B) ? __ldg(&feats[(size_t)row * 784 + k]) : 0.f;
        rb[j] = __ldg(&W1v4[tid + j * 256]);
    }
    // store chunk 0
#pragma unroll
    for (int j = 0; j < 7; j++) {
        int i = tid + j * 256;
        int r = i / KT, k = i - r * KT;
        sA[r * SA_STRIDE + k] = ra[j];
        reinterpret_cast<float4*>(sB)[tid + j * 256] = rb[j];
    }
    __syncthreads();

    const float* Ab0 = sA + (2 * tr) * SA_STRIDE;
    const float* Ab1 = Ab0 + SA_STRIDE;
    const float* Bb  = sB + tc * 8;

    for (int cch = 0; cch < NCHUNK; cch++) {
        // prefetch next chunk into registers (LDG latency hidden by compute)
        if (cch < NCHUNK - 1) {
            int k0n = (cch + 1) * KT;
#pragma unroll
            for (int j = 0; j < 7; j++) {
                int i = tid + j * 256;
                int r = i / KT, k = i - r * KT;
                int row = row0 + r;
                ra[j] = (row < B) ? __ldg(&feats[(size_t)row * 784 + k0n + k]) : 0.f;
                rb[j] = __ldg(&W1v4[k0n * 32 + tid + j * 256]);
            }
        }
        // compute current chunk
#pragma unroll 8
        for (int k = 0; k < KT; k++) {
            float a0 = Ab0[k];
            float a1 = Ab1[k];
            float4 bv0 = *reinterpret_cast<const float4*>(Bb + k * 128);
            float4 bv1 = *reinterpret_cast<const float4*>(Bb + k * 128 + 4);
            float bb[8] = {bv0.x, bv0.y, bv0.z, bv0.w, bv1.x, bv1.y, bv1.z, bv1.w};
#pragma unroll
            for (int j = 0; j < 8; j++) {
                acc[0][j] = fmaf(a0, bb[j], acc[0][j]);
                acc[1][j] = fmaf(a1, bb[j], acc[1][j]);
            }
        }
        __syncthreads();
        if (cch < NCHUNK - 1) {
#pragma unroll
            for (int j = 0; j < 7; j++) {
                int i = tid + j * 256;
                int r = i / KT, k = i - r * KT;
                sA[r * SA_STRIDE + k] = ra[j];
                reinterpret_cast<float4*>(sB)[tid + j * 256] = rb[j];
            }
            __syncthreads();
        }
    }

    // ---- epilogue: bias + relu; stage h into smem (reuse sB) ----
    float* sH = sB;   // [32][SH_STRIDE]
#pragma unroll
    for (int a = 0; a < 2; a++) {
        int r = 2 * tr + a;
        float4 h0, h1;
        h0.x = fmaxf(acc[a][0] + sb1v[tc * 8 + 0], 0.f);
        h0.y = fmaxf(acc[a][1] + sb1v[tc * 8 + 1], 0.f);
        h0.z = fmaxf(acc[a][2] + sb1v[tc * 8 + 2], 0.f);
        h0.w = fmaxf(acc[a][3] + sb1v[tc * 8 + 3], 0.f);
        h1.x = fmaxf(acc[a][4] + sb1v[tc * 8 + 4], 0.f);
        h1.y = fmaxf(acc[a][5] + sb1v[tc * 8 + 5], 0.f);
        h1.z = fmaxf(acc[a][6] + sb1v[tc * 8 + 6], 0.f);
        h1.w = fmaxf(acc[a][7] + sb1v[tc * 8 + 7], 0.f);
        *reinterpret_cast<float4*>(&sH[r * SH_STRIDE + tc * 8])     = h0;
        *reinterpret_cast<float4*>(&sH[r * SH_STRIDE + tc * 8 + 4]) = h1;
    }
    __syncthreads();

    // ---- second GEMM (128 -> 10) + log_softmax. Warp w handles rows 4w..4w+3.
    int warp = tid >> 5;
    int lane = tid & 31;
#pragma unroll
    for (int rr = 0; rr < 4; rr++) {
        int r = warp * 4 + rr;
        float hv[4];
#pragma unroll
        for (int j = 0; j < 4; j++) hv[j] = sH[r * SH_STRIDE + lane + 32 * j];
        float lg[10];
#pragma unroll
        for (int q = 0; q < 10; q++) lg[q] = 0.f;
#pragma unroll
        for (int j = 0; j < 4; j++) {
#pragma unroll
            for (int q = 0; q < 10; q++)
                lg[q] = fmaf(hv[j], sW2t[q * 128 + lane + 32 * j], lg[q]);
        }
#pragma unroll
        for (int off = 16; off; off >>= 1)
#pragma unroll
            for (int q = 0; q < 10; q++)
                lg[q] += __shfl_xor_sync(0xffffffffu, lg[q], off);

        if (lane == 0) {
            int row = row0 + r;
            if (row < B) {
                float l[10];
                float m = -1e30f;
#pragma unroll
                for (int q = 0; q < 10; q++) {
                    l[q] = lg[q] + __ldg(&b2[q]);
                    m = fmaxf(m, l[q]);
                }
                float se = 0.f;
#pragma unroll
                for (int q = 0; q < 10; q++) se += expf(l[q] - m);
                float lse = m + logf(se);
#pragma unroll
                for (int q = 0; q < 10; q++)
                    out[(size_t)row * 10 + q] = l[q] - lse;
            }
        }
    }
}

// ================================ launch ===================================
extern "C" void kernel_launch(void* const* d_in, const int* in_sizes, int n_in,
                              void* d_out, int out_size) {
    const float* x     = (const float*)d_in[0];   // [B, 784]
    const float* theta = (const float*)d_in[1];   // [2, 4]
    const float* W1    = (const float*)d_in[2];   // [784, 128]
    const float* b1    = (const float*)d_in[3];   // [128]
    const float* W2    = (const float*)d_in[4];   // [128, 10]
    const float* b2    = (const float*)d_in[5];   // [10]
    float* out = (float*)d_out;

    int B = in_sizes[0] / 784;
    if (B > MAX_B) B = MAX_B;

    float* feats;
    cudaGetSymbolAddress((void**)&feats, g_feats);

    int total = B * 196;
    int blocks1 = (total + 255) / 256;
    quanv_kernel<<<blocks1, 256>>>(x, theta, feats, B);

    int blocks2 = (B + BR - 1) / BR;
    mlp_kernel<<<blocks2, 256>>>(feats, W1, b1, W2, b2, out, B);
}